// round 1
// baseline (speedup 1.0000x reference)
#include <cuda_runtime.h>

#define BQ    8
#define CINC  128
#define COUTC 128
#define HH    256
#define WW    256
#define HEADS 32
#define CIH   4
#define HWSZ  (HH * WW)        /* 65536 */
#define TOT   (BQ * HWSZ)      /* 524288 */

// Scratch (allocation-free rule: __device__ globals).
// g_value layout: [((b*HEADS + head)*HW + hw)*4 + ci]  -> float4 per (pixel, head)
// g_flow  layout: [n * TOT + m], n = head*2 + dir, m = b*HW + hw
__device__ float g_value[(size_t)TOT * COUTC];
__device__ float g_flow[(size_t)(2 * HEADS) * TOT];

// ---------------------------------------------------------------------------
// Kernel 1: value = u @ w_v^T + b_v   (M=TOT, N=128, K=128)
// 128x128 tile per block, 256 threads, 8x8 register tile, BK=16.
// ---------------------------------------------------------------------------
__global__ __launch_bounds__(256) void value_kernel(const float* __restrict__ u,
                                                    const float* __restrict__ wv,
                                                    const float* __restrict__ bv) {
    __shared__ float As[16][128];
    __shared__ float Bs[16][128];

    const int t  = threadIdx.x;
    const int tx = t & 15;
    const int ty = t >> 4;
    const int m0  = blockIdx.x * 128;
    const int b   = m0 / HWSZ;
    const int hw0 = m0 - b * HWSZ;
    const float* uB = u + (size_t)b * CINC * HWSZ + hw0;

    float acc[8][8];
#pragma unroll
    for (int i = 0; i < 8; ++i)
#pragma unroll
        for (int j = 0; j < 8; ++j) acc[i][j] = 0.0f;

    for (int k0 = 0; k0 < CINC; k0 += 16) {
        // A tile: As[k][m] (16 x 128) via float4, fully coalesced
        {
            const int r  = t >> 4;   // k row 0..15
            const int c4 = t & 15;   // float4 col
            const float4* src = (const float4*)(uB + (size_t)(k0 + r) * HWSZ);
            *(float4*)&As[r][c4 * 4]        = src[c4];
            *(float4*)&As[r][(c4 + 16) * 4] = src[c4 + 16];
        }
        // B tile: Bs[k][n] = wv[n*128 + k0 + k]
        {
            const int n  = t >> 1;
            const int kc = t & 1;
#pragma unroll
            for (int hh = 0; hh < 2; ++hh) {
                const int kk4 = (kc + 2 * hh) * 4;
                float4 v = *(const float4*)(wv + n * CINC + k0 + kk4);
                Bs[kk4 + 0][n] = v.x; Bs[kk4 + 1][n] = v.y;
                Bs[kk4 + 2][n] = v.z; Bs[kk4 + 3][n] = v.w;
            }
        }
        __syncthreads();
#pragma unroll
        for (int kk = 0; kk < 16; ++kk) {
            float a[8], bb[8];
#pragma unroll
            for (int i = 0; i < 8; ++i) a[i] = As[kk][ty + 16 * i];
#pragma unroll
            for (int j = 0; j < 8; ++j) bb[j] = Bs[kk][tx + 16 * j];
#pragma unroll
            for (int i = 0; i < 8; ++i)
#pragma unroll
                for (int j = 0; j < 8; ++j) acc[i][j] += a[i] * bb[j];
        }
        __syncthreads();
    }

    // Epilogue: head-interleaved float4 layout for fast gathers later.
    const size_t bOff = (size_t)b * HWSZ * COUTC;
#pragma unroll
    for (int j = 0; j < 8; ++j) {
        const int o    = tx + 16 * j;
        const float bi = bv[o];
        const int head = o >> 2;
        const int ci   = o & 3;
#pragma unroll
        for (int i = 0; i < 8; ++i) {
            const int hw = hw0 + ty + 16 * i;
            g_value[bOff + ((size_t)head * HWSZ + hw) * 4 + ci] = acc[i][j] + bi;
        }
    }
}

// ---------------------------------------------------------------------------
// Kernel 2: hmid = relu(u @ w_f1^T + b_f1); flow = hmid @ w_f2^T + b_f2
// Fused per 128-pixel tile. Dynamic smem.
// smem layout (floats): As[2048] | Bs[2048] | wf2s[128*65] | hm[128*129]
// flow staging reuses hm region (64*130 floats).
// ---------------------------------------------------------------------------
#define FK_AS   0
#define FK_BS   2048
#define FK_WF2  4096
#define FK_HM   (4096 + 128 * 65)
#define FK_SMEM_FLOATS (FK_HM + 128 * 129)
#define FK_SMEM_BYTES  (FK_SMEM_FLOATS * 4)

__global__ __launch_bounds__(256) void flow_kernel(const float* __restrict__ u,
                                                   const float* __restrict__ wf1,
                                                   const float* __restrict__ bf1,
                                                   const float* __restrict__ wf2,
                                                   const float* __restrict__ bf2) {
    extern __shared__ float sm[];
    float* As   = sm + FK_AS;    // [16][128]
    float* Bs   = sm + FK_BS;    // [16][128]
    float* wf2s = sm + FK_WF2;   // [128][65] (pitch 65)
    float* hm   = sm + FK_HM;    // [128][129] (pitch 129), later flow_s [64][130]

    const int t  = threadIdx.x;
    const int tx = t & 15;
    const int ty = t >> 4;
    const int m0  = blockIdx.x * 128;
    const int b   = m0 / HWSZ;
    const int hw0 = m0 - b * HWSZ;
    const float* uB = u + (size_t)b * CINC * HWSZ + hw0;

    // preload w_f2 (64x128) transposed into smem: wf2s[k*65 + n2]
    for (int idx = t; idx < 64 * 128; idx += 256) {
        const int n2 = idx >> 7;
        const int k  = idx & 127;
        wf2s[k * 65 + n2] = wf2[idx];
    }

    float acc[8][8];
#pragma unroll
    for (int i = 0; i < 8; ++i)
#pragma unroll
        for (int j = 0; j < 8; ++j) acc[i][j] = 0.0f;

    for (int k0 = 0; k0 < CINC; k0 += 16) {
        {
            const int r  = t >> 4;
            const int c4 = t & 15;
            const float4* src = (const float4*)(uB + (size_t)(k0 + r) * HWSZ);
            *(float4*)&As[r * 128 + c4 * 4]        = src[c4];
            *(float4*)&As[r * 128 + (c4 + 16) * 4] = src[c4 + 16];
        }
        {
            const int n  = t >> 1;
            const int kc = t & 1;
#pragma unroll
            for (int hh = 0; hh < 2; ++hh) {
                const int kk4 = (kc + 2 * hh) * 4;
                float4 v = *(const float4*)(wf1 + n * CINC + k0 + kk4);
                Bs[(kk4 + 0) * 128 + n] = v.x; Bs[(kk4 + 1) * 128 + n] = v.y;
                Bs[(kk4 + 2) * 128 + n] = v.z; Bs[(kk4 + 3) * 128 + n] = v.w;
            }
        }
        __syncthreads();
#pragma unroll
        for (int kk = 0; kk < 16; ++kk) {
            float a[8], bb[8];
#pragma unroll
            for (int i = 0; i < 8; ++i) a[i] = As[kk * 128 + ty + 16 * i];
#pragma unroll
            for (int j = 0; j < 8; ++j) bb[j] = Bs[kk * 128 + tx + 16 * j];
#pragma unroll
            for (int i = 0; i < 8; ++i)
#pragma unroll
                for (int j = 0; j < 8; ++j) acc[i][j] += a[i] * bb[j];
        }
        __syncthreads();
    }

    // relu(hmid + bias) -> hm[n][m] (pitch 129)
#pragma unroll
    for (int j = 0; j < 8; ++j) {
        const int o    = tx + 16 * j;
        const float bi = bf1[o];
#pragma unroll
        for (int i = 0; i < 8; ++i) {
            hm[o * 129 + ty + 16 * i] = fmaxf(acc[i][j] + bi, 0.0f);
        }
    }
    __syncthreads();

    // GEMM2: flow[m][n2] = sum_k hm[m][k] * wf2[n2][k]
    float acc2[8][4];
#pragma unroll
    for (int i = 0; i < 8; ++i)
#pragma unroll
        for (int j = 0; j < 4; ++j) acc2[i][j] = 0.0f;

#pragma unroll 4
    for (int k = 0; k < 128; ++k) {
        float a2[8], b2[4];
#pragma unroll
        for (int i = 0; i < 8; ++i) a2[i] = hm[k * 129 + ty + 16 * i];
#pragma unroll
        for (int j = 0; j < 4; ++j) b2[j] = wf2s[k * 65 + tx + 16 * j];
#pragma unroll
        for (int i = 0; i < 8; ++i)
#pragma unroll
            for (int j = 0; j < 4; ++j) acc2[i][j] += a2[i] * b2[j];
    }
    __syncthreads();

    // stage flow into smem (pitch 130, conflict-free) then coalesced store
    float* flow_s = hm;  // reuse
#pragma unroll
    for (int j = 0; j < 4; ++j) {
        const int n2   = tx + 16 * j;
        const float bi = bf2[n2];
#pragma unroll
        for (int i = 0; i < 8; ++i) {
            flow_s[n2 * 130 + ty + 16 * i] = acc2[i][j] + bi;
        }
    }
    __syncthreads();
    for (int idx = t; idx < 64 * 128; idx += 256) {
        const int n2 = idx >> 7;
        const int m  = idx & 127;
        g_flow[(size_t)n2 * TOT + m0 + m] = flow_s[n2 * 130 + m];
    }
}

// ---------------------------------------------------------------------------
// Kernel 3: periodic bilinear warp. One lane per (pixel, head).
// ---------------------------------------------------------------------------
__global__ __launch_bounds__(256) void sample_kernel(float* __restrict__ out) {
    const int gt    = blockIdx.x * 256 + threadIdx.x;
    const int lane  = gt & 31;
    const int strip = gt >> 5;                 // 0 .. B*HEADS*(HW/32)-1
    const int chunk = strip & (HWSZ / 32 - 1); // 0..2047
    const int bh    = strip >> 11;             // b*HEADS + head
    const int head  = bh & (HEADS - 1);
    const int b     = bh >> 5;
    const int hw    = chunk * 32 + lane;
    const int h     = hw >> 8;
    const int w     = hw & 255;
    const size_t m  = (size_t)b * HWSZ + hw;

    const float fx = g_flow[(size_t)(head * 2) * TOT + m];
    const float fy = g_flow[(size_t)(head * 2 + 1) * TOT + m];

    const float gx = -1.0f + (2.0f / 255.0f) * (float)w + fx;
    const float gy = -1.0f + (2.0f / 255.0f) * (float)h + fy;

    const float ax = ((gx + 1.0f) * 256.0f - 1.0f) * 0.5f;
    const float ay = ((gy + 1.0f) * 256.0f - 1.0f) * 0.5f;

    float px = fmodf(ax, 256.0f); if (px < 0.0f) px += 256.0f;
    float py = fmodf(ay, 256.0f); if (py < 0.0f) py += 256.0f;

    const float x0f = floorf(px), y0f = floorf(py);
    const float wx = px - x0f, wy = py - y0f;
    int x0 = (int)x0f; x0 = x0 < 0 ? 0 : (x0 > 255 ? 255 : x0);
    int y0 = (int)y0f; y0 = y0 < 0 ? 0 : (y0 > 255 ? 255 : y0);
    const int x1 = (x0 + 1) & 255;
    const int y1 = (y0 + 1) & 255;

    const float4* vp = (const float4*)g_value + (size_t)bh * HWSZ;
    const float4 v00 = vp[y0 * 256 + x0];
    const float4 v01 = vp[y0 * 256 + x1];
    const float4 v10 = vp[y1 * 256 + x0];
    const float4 v11 = vp[y1 * 256 + x1];

    const float w00 = (1.0f - wx) * (1.0f - wy);
    const float w01 = wx * (1.0f - wy);
    const float w10 = (1.0f - wx) * wy;
    const float w11 = wx * wy;

    const float o0 = v00.x * w00 + v01.x * w01 + v10.x * w10 + v11.x * w11;
    const float o1 = v00.y * w00 + v01.y * w01 + v10.y * w10 + v11.y * w11;
    const float o2 = v00.z * w00 + v01.z * w01 + v10.z * w10 + v11.z * w11;
    const float o3 = v00.w * w00 + v01.w * w01 + v10.w * w10 + v11.w * w11;

    float* outp = out + ((size_t)b * COUTC + head * 4) * HWSZ + hw;
    outp[0]         = o0;
    outp[HWSZ]      = o1;
    outp[2 * HWSZ]  = o2;
    outp[3 * HWSZ]  = o3;
}

// ---------------------------------------------------------------------------
extern "C" void kernel_launch(void* const* d_in, const int* in_sizes, int n_in,
                              void* d_out, int out_size) {
    const float* u   = (const float*)d_in[0];
    const float* wf1 = (const float*)d_in[1];
    const float* bf1 = (const float*)d_in[2];
    const float* wf2 = (const float*)d_in[3];
    const float* bf2 = (const float*)d_in[4];
    const float* wv  = (const float*)d_in[5];
    const float* bv  = (const float*)d_in[6];
    float* out = (float*)d_out;

    cudaFuncSetAttribute(flow_kernel, cudaFuncAttributeMaxDynamicSharedMemorySize,
                         FK_SMEM_BYTES);

    const int gemm_blocks = TOT / 128;  // 4096
    value_kernel<<<gemm_blocks, 256>>>(u, wv, bv);
    flow_kernel<<<gemm_blocks, 256, FK_SMEM_BYTES>>>(u, wf1, bf1, wf2, bf2);

    const long long items = (long long)BQ * HEADS * HWSZ;  // 16.78M
    sample_kernel<<<(int)(items / 256), 256>>>(out);
}

// round 2
// speedup vs baseline: 1.2033x; 1.2033x over previous
#include <cuda_runtime.h>

#define BQ    8
#define CINC  128
#define COUTC 128
#define HH    256
#define WW    256
#define HEADS 32
#define HWSZ  (HH * WW)        /* 65536 */
#define TOT   (BQ * HWSZ)      /* 524288 */

// Scratch (allocation-free rule: __device__ globals).
// g_value layout: [((b*HEADS + head)*HW + hw)*4 + ci]  -> float4 per (pixel, head)
// g_flow  layout: [n * TOT + m], n = head*2 + dir, m = b*HW + hw
__device__ __align__(16) float g_value[(size_t)TOT * COUTC];
__device__ __align__(16) float g_flow[(size_t)(2 * HEADS) * TOT];

// ---------------------------------------------------------------------------
// Packed fp32x2 helpers (Blackwell double-rate fp32 path; FFMA2 in SASS).
// low 32 bits = first element.
// ---------------------------------------------------------------------------
__device__ __forceinline__ unsigned long long pack_dup(float x) {
    unsigned long long r;
    asm("mov.b64 %0, {%1, %1};" : "=l"(r) : "f"(x));
    return r;
}
__device__ __forceinline__ void unpack2(unsigned long long p, float& lo, float& hi) {
    asm("mov.b64 {%0, %1}, %2;" : "=f"(lo), "=f"(hi) : "l"(p));
}
__device__ __forceinline__ unsigned long long ffma2(unsigned long long a,
                                                    unsigned long long b,
                                                    unsigned long long c) {
    unsigned long long d;
    asm("fma.rn.f32x2 %0, %1, %2, %3;" : "=l"(d) : "l"(a), "l"(b), "l"(c));
    return d;
}

// ---------------------------------------------------------------------------
// Kernel 1: value = u @ w_v^T + b_v   (M=TOT, N=128, K=128)
// 128x128 tile, 256 threads, 8(m) x 4(n-pair) register tile, BK=16, f32x2.
// Thread n indices: n = 2*tx + 32*jp + {0,1}
// ---------------------------------------------------------------------------
__global__ __launch_bounds__(256, 2) void value_kernel(const float* __restrict__ u,
                                                       const float* __restrict__ wv,
                                                       const float* __restrict__ bv) {
    __shared__ float As[16][128];
    __shared__ float Bs[16][128];

    const int t  = threadIdx.x;
    const int tx = t & 15;
    const int ty = t >> 4;
    const int m0  = blockIdx.x * 128;
    const int b   = m0 / HWSZ;
    const int hw0 = m0 - b * HWSZ;
    const float* uB = u + (size_t)b * CINC * HWSZ + hw0;

    unsigned long long acc[8][4];
#pragma unroll
    for (int i = 0; i < 8; ++i)
#pragma unroll
        for (int jp = 0; jp < 4; ++jp) acc[i][jp] = 0ULL;

    for (int k0 = 0; k0 < CINC; k0 += 16) {
        {
            const int r  = t >> 4;   // k row 0..15
            const int c4 = t & 15;   // float4 col
            const float4* src = (const float4*)(uB + (size_t)(k0 + r) * HWSZ);
            *(float4*)&As[r][c4 * 4]        = src[c4];
            *(float4*)&As[r][(c4 + 16) * 4] = src[c4 + 16];
        }
        {
            const int n  = t >> 1;
            const int kc = t & 1;
#pragma unroll
            for (int hh = 0; hh < 2; ++hh) {
                const int kk4 = (kc + 2 * hh) * 4;
                float4 v = *(const float4*)(wv + n * CINC + k0 + kk4);
                Bs[kk4 + 0][n] = v.x; Bs[kk4 + 1][n] = v.y;
                Bs[kk4 + 2][n] = v.z; Bs[kk4 + 3][n] = v.w;
            }
        }
        __syncthreads();
#pragma unroll
        for (int kk = 0; kk < 16; ++kk) {
            unsigned long long ad[8], bp[4];
#pragma unroll
            for (int i = 0; i < 8; ++i) ad[i] = pack_dup(As[kk][ty + 16 * i]);
#pragma unroll
            for (int jp = 0; jp < 4; ++jp)
                bp[jp] = *(const unsigned long long*)&Bs[kk][2 * tx + 32 * jp];
#pragma unroll
            for (int i = 0; i < 8; ++i)
#pragma unroll
                for (int jp = 0; jp < 4; ++jp)
                    acc[i][jp] = ffma2(ad[i], bp[jp], acc[i][jp]);
        }
        __syncthreads();
    }

    // Epilogue: head-interleaved float4 layout (n pair -> adjacent ci -> float2 store)
    const size_t bOff = (size_t)b * HWSZ * COUTC;
#pragma unroll
    for (int jp = 0; jp < 4; ++jp) {
        const int n0 = 2 * tx + 32 * jp;
        const float b0 = bv[n0], b1 = bv[n0 + 1];
        const int head = n0 >> 2;
        const int ci   = n0 & 3;   // 0 or 2, pair stays inside one head
#pragma unroll
        for (int i = 0; i < 8; ++i) {
            const int hw = hw0 + ty + 16 * i;
            float lo, hi; unpack2(acc[i][jp], lo, hi);
            float2 st; st.x = lo + b0; st.y = hi + b1;
            *(float2*)&g_value[bOff + ((size_t)head * HWSZ + hw) * 4 + ci] = st;
        }
    }
}

// ---------------------------------------------------------------------------
// Kernel 2: hmid = relu(u @ w_f1^T + b_f1); flow = hmid @ w_f2^T + b_f2
// Fused per 128-pixel tile. GEMM2 K-split in two halves -> hm buffer halved,
// smem ~83KB -> 2 CTAs/SM.
// smem (floats): As[2048] | Bs[2048] | wf2s[128*66] | hm[64*129]
// ---------------------------------------------------------------------------
#define FK_AS   0
#define FK_BS   2048
#define FK_WF2  4096
#define FK_HM   (4096 + 128 * 66)
#define FK_SMEM_FLOATS (FK_HM + 64 * 129)
#define FK_SMEM_BYTES  (FK_SMEM_FLOATS * 4)

__global__ __launch_bounds__(256, 2) void flow_kernel(const float* __restrict__ u,
                                                      const float* __restrict__ wf1,
                                                      const float* __restrict__ bf1,
                                                      const float* __restrict__ wf2,
                                                      const float* __restrict__ bf2) {
    extern __shared__ float sm[];
    float* As   = sm + FK_AS;    // [16][128]
    float* Bs   = sm + FK_BS;    // [16][128]
    float* wf2s = sm + FK_WF2;   // [128][66] pitch 66 (8B-aligned pairs)
    float* hm   = sm + FK_HM;    // [64][129], later flow staging

    const int t  = threadIdx.x;
    const int tx = t & 15;
    const int ty = t >> 4;
    const int m0  = blockIdx.x * 128;
    const int b   = m0 / HWSZ;
    const int hw0 = m0 - b * HWSZ;
    const float* uB = u + (size_t)b * CINC * HWSZ + hw0;

    // preload w_f2 (64x128) transposed: wf2s[k*66 + n2]
    for (int idx = t; idx < 64 * 128; idx += 256) {
        const int n2 = idx >> 7;
        const int k  = idx & 127;
        wf2s[k * 66 + n2] = wf2[idx];
    }

    unsigned long long acc[8][4];
#pragma unroll
    for (int i = 0; i < 8; ++i)
#pragma unroll
        for (int jp = 0; jp < 4; ++jp) acc[i][jp] = 0ULL;

    for (int k0 = 0; k0 < CINC; k0 += 16) {
        {
            const int r  = t >> 4;
            const int c4 = t & 15;
            const float4* src = (const float4*)(uB + (size_t)(k0 + r) * HWSZ);
            *(float4*)&As[r * 128 + c4 * 4]        = src[c4];
            *(float4*)&As[r * 128 + (c4 + 16) * 4] = src[c4 + 16];
        }
        {
            const int n  = t >> 1;
            const int kc = t & 1;
#pragma unroll
            for (int hh = 0; hh < 2; ++hh) {
                const int kk4 = (kc + 2 * hh) * 4;
                float4 v = *(const float4*)(wf1 + n * CINC + k0 + kk4);
                Bs[(kk4 + 0) * 128 + n] = v.x; Bs[(kk4 + 1) * 128 + n] = v.y;
                Bs[(kk4 + 2) * 128 + n] = v.z; Bs[(kk4 + 3) * 128 + n] = v.w;
            }
        }
        __syncthreads();
#pragma unroll
        for (int kk = 0; kk < 16; ++kk) {
            unsigned long long ad[8], bp[4];
#pragma unroll
            for (int i = 0; i < 8; ++i) ad[i] = pack_dup(As[kk * 128 + ty + 16 * i]);
#pragma unroll
            for (int jp = 0; jp < 4; ++jp)
                bp[jp] = *(const unsigned long long*)&Bs[kk * 128 + 2 * tx + 32 * jp];
#pragma unroll
            for (int i = 0; i < 8; ++i)
#pragma unroll
                for (int jp = 0; jp < 4; ++jp)
                    acc[i][jp] = ffma2(ad[i], bp[jp], acc[i][jp]);
        }
        __syncthreads();
    }

    // GEMM2: flow[m][n2] = sum_k relu(hmid)[m][k] * wf2[n2][k], K split in 2 halves.
    unsigned long long acc2[8][2];
#pragma unroll
    for (int i = 0; i < 8; ++i)
#pragma unroll
        for (int jp = 0; jp < 2; ++jp) acc2[i][jp] = 0ULL;

#pragma unroll
    for (int h = 0; h < 2; ++h) {
        // write relu(hmid)+bias for o in [64h, 64h+64) into hm (local o0 = o - 64h)
#pragma unroll
        for (int jp = 2 * h; jp < 2 * h + 2; ++jp) {
            const int n0 = 2 * tx + 32 * jp;          // global o (even)
            const int o0 = n0 - 64 * h;               // local 0..62 even
            const float b0 = bf1[n0], b1 = bf1[n0 + 1];
#pragma unroll
            for (int i = 0; i < 8; ++i) {
                const int m = ty + 16 * i;
                float lo, hi; unpack2(acc[i][jp], lo, hi);
                hm[o0 * 129 + m]       = fmaxf(lo + b0, 0.0f);
                hm[(o0 + 1) * 129 + m] = fmaxf(hi + b1, 0.0f);
            }
        }
        __syncthreads();
        // accumulate k = 64h .. 64h+63
#pragma unroll 4
        for (int kk = 0; kk < 64; ++kk) {
            const int k = 64 * h + kk;
            unsigned long long ad[8], bp[2];
#pragma unroll
            for (int i = 0; i < 8; ++i) ad[i] = pack_dup(hm[kk * 129 + ty + 16 * i]);
#pragma unroll
            for (int jp = 0; jp < 2; ++jp)
                bp[jp] = *(const unsigned long long*)&wf2s[k * 66 + 2 * tx + 32 * jp];
#pragma unroll
            for (int i = 0; i < 8; ++i)
#pragma unroll
                for (int jp = 0; jp < 2; ++jp)
                    acc2[i][jp] = ffma2(ad[i], bp[jp], acc2[i][jp]);
        }
        __syncthreads();
    }

    // stage flow into smem (reuse hm: [64][129]) then coalesced store
#pragma unroll
    for (int jp = 0; jp < 2; ++jp) {
        const int n2 = 2 * tx + 32 * jp;
        const float b0 = bf2[n2], b1 = bf2[n2 + 1];
#pragma unroll
        for (int i = 0; i < 8; ++i) {
            const int m = ty + 16 * i;
            float lo, hi; unpack2(acc2[i][jp], lo, hi);
            hm[n2 * 129 + m]       = lo + b0;
            hm[(n2 + 1) * 129 + m] = hi + b1;
        }
    }
    __syncthreads();
    for (int idx = t; idx < 64 * 128; idx += 256) {
        const int n2 = idx >> 7;
        const int m  = idx & 127;
        g_flow[(size_t)n2 * TOT + m0 + m] = hm[n2 * 129 + m];
    }
}

// ---------------------------------------------------------------------------
// Kernel 3: periodic bilinear warp. One lane per (pixel, head).
// ---------------------------------------------------------------------------
__global__ __launch_bounds__(256) void sample_kernel(float* __restrict__ out) {
    const int gt    = blockIdx.x * 256 + threadIdx.x;
    const int lane  = gt & 31;
    const int strip = gt >> 5;
    const int chunk = strip & (HWSZ / 32 - 1);
    const int bh    = strip >> 11;             // b*HEADS + head
    const int head  = bh & (HEADS - 1);
    const int b     = bh >> 5;
    const int hw    = chunk * 32 + lane;
    const int h     = hw >> 8;
    const int w     = hw & 255;
    const size_t m  = (size_t)b * HWSZ + hw;

    const float fx = g_flow[(size_t)(head * 2) * TOT + m];
    const float fy = g_flow[(size_t)(head * 2 + 1) * TOT + m];

    const float gx = -1.0f + (2.0f / 255.0f) * (float)w + fx;
    const float gy = -1.0f + (2.0f / 255.0f) * (float)h + fy;

    const float ax = ((gx + 1.0f) * 256.0f - 1.0f) * 0.5f;
    const float ay = ((gy + 1.0f) * 256.0f - 1.0f) * 0.5f;

    float px = fmodf(ax, 256.0f); if (px < 0.0f) px += 256.0f;
    float py = fmodf(ay, 256.0f); if (py < 0.0f) py += 256.0f;

    const float x0f = floorf(px), y0f = floorf(py);
    const float wx = px - x0f, wy = py - y0f;
    int x0 = (int)x0f; x0 = x0 < 0 ? 0 : (x0 > 255 ? 255 : x0);
    int y0 = (int)y0f; y0 = y0 < 0 ? 0 : (y0 > 255 ? 255 : y0);
    const int x1 = (x0 + 1) & 255;
    const int y1 = (y0 + 1) & 255;

    const float4* vp = (const float4*)g_value + (size_t)bh * HWSZ;
    const float4 v00 = vp[y0 * 256 + x0];
    const float4 v01 = vp[y0 * 256 + x1];
    const float4 v10 = vp[y1 * 256 + x0];
    const float4 v11 = vp[y1 * 256 + x1];

    const float w00 = (1.0f - wx) * (1.0f - wy);
    const float w01 = wx * (1.0f - wy);
    const float w10 = (1.0f - wx) * wy;
    const float w11 = wx * wy;

    const float o0 = v00.x * w00 + v01.x * w01 + v10.x * w10 + v11.x * w11;
    const float o1 = v00.y * w00 + v01.y * w01 + v10.y * w10 + v11.y * w11;
    const float o2 = v00.z * w00 + v01.z * w01 + v10.z * w10 + v11.z * w11;
    const float o3 = v00.w * w00 + v01.w * w01 + v10.w * w10 + v11.w * w11;

    float* outp = out + ((size_t)b * COUTC + head * 4) * HWSZ + hw;
    outp[0]         = o0;
    outp[HWSZ]      = o1;
    outp[2 * HWSZ]  = o2;
    outp[3 * HWSZ]  = o3;
}

// ---------------------------------------------------------------------------
extern "C" void kernel_launch(void* const* d_in, const int* in_sizes, int n_in,
                              void* d_out, int out_size) {
    const float* u   = (const float*)d_in[0];
    const float* wf1 = (const float*)d_in[1];
    const float* bf1 = (const float*)d_in[2];
    const float* wf2 = (const float*)d_in[3];
    const float* bf2 = (const float*)d_in[4];
    const float* wv  = (const float*)d_in[5];
    const float* bv  = (const float*)d_in[6];
    float* out = (float*)d_out;

    cudaFuncSetAttribute(flow_kernel, cudaFuncAttributeMaxDynamicSharedMemorySize,
                         FK_SMEM_BYTES);

    const int gemm_blocks = TOT / 128;  // 4096
    value_kernel<<<gemm_blocks, 256>>>(u, wv, bv);
    flow_kernel<<<gemm_blocks, 256, FK_SMEM_BYTES>>>(u, wf1, bf1, wf2, bf2);

    const long long items = (long long)BQ * HEADS * HWSZ;  // 16.78M
    sample_kernel<<<(int)(items / 256), 256>>>(out);
}

// round 4
// speedup vs baseline: 1.6453x; 1.3673x over previous
#include <cuda_runtime.h>
#include <cstdint>

#define BQ    8
#define CINC  128
#define COUTC 128
#define HH    256
#define WW    256
#define HEADS 32
#define HWSZ  (HH * WW)        /* 65536 */
#define TOT   (BQ * HWSZ)      /* 524288 */

// Scratch globals (allocation-free rule).
// g_value: [((b*32+head)*HW + hw)*4 + ci] -> float4 per (pixel, head)
// g_flow:  [n2 * TOT + b*HW + hw]
__device__ __align__(16) float g_value[(size_t)TOT * COUTC];
__device__ __align__(16) float g_flow[(size_t)(2 * HEADS) * TOT];

// Pre-packed bf16 hi/lo weight fragments in m16n8k16 B-operand order.
// Index: (nt*8 + kt)*32 + lane ; each entry = {b0, b1} (.b32 regs).
__device__ __align__(16) uint2 g_wv_hi[4096],  g_wv_lo[4096];   // 16 ntiles
__device__ __align__(16) uint2 g_wf1_hi[4096], g_wf1_lo[4096];  // 16 ntiles
__device__ __align__(16) uint2 g_wf2_hi[2048], g_wf2_lo[2048];  // 8 ntiles

// ---------------------------------------------------------------------------
// helpers
// ---------------------------------------------------------------------------
// Pack two floats into bf16x2 (v0 -> low half, v1 -> high half), rn rounding,
// and produce the residual (lo) pack as well:  v ~= hi + lo  per element.
__device__ __forceinline__ void split2(float v0, float v1, uint32_t& hi, uint32_t& lo) {
    asm("cvt.rn.bf16x2.f32 %0, %1, %2;" : "=r"(hi) : "f"(v1), "f"(v0));
    const float h0 = __uint_as_float(hi << 16);
    const float h1 = __uint_as_float(hi & 0xffff0000u);
    const float r0 = v0 - h0;
    const float r1 = v1 - h1;
    asm("cvt.rn.bf16x2.f32 %0, %1, %2;" : "=r"(lo) : "f"(r1), "f"(r0));
}
// m16n8k16 row.col bf16 MMA, fp32 accumulate in-place.
__device__ __forceinline__ void mma16816(float* c, uint32_t a0, uint32_t a1,
                                         uint32_t a2, uint32_t a3,
                                         uint32_t b0, uint32_t b1) {
    asm volatile(
        "mma.sync.aligned.m16n8k16.row.col.f32.bf16.bf16.f32 "
        "{%0,%1,%2,%3}, {%4,%5,%6,%7}, {%8,%9}, {%0,%1,%2,%3};"
        : "+f"(c[0]), "+f"(c[1]), "+f"(c[2]), "+f"(c[3])
        : "r"(a0), "r"(a1), "r"(a2), "r"(a3), "r"(b0), "r"(b1));
}

// ---------------------------------------------------------------------------
// Kernel 0: pack weights into bf16 hi/lo B-fragments.
// idx = nt*256 + kt*32 + lane ; n = nt*8 + lane/4 ; k0 = kt*16 + 2*(lane%4)
// b0 = (k0,k0+1), b1 = (k0+8,k0+9) for column n.
// ---------------------------------------------------------------------------
__global__ void split_weights(const float* __restrict__ wv,
                              const float* __restrict__ wf1,
                              const float* __restrict__ wf2) {
    const int idx  = blockIdx.x * 256 + threadIdx.x;  // 0..4095 (grid=16)
    const int lane = idx & 31;
    const int kt   = (idx >> 5) & 7;
    const int nt   = idx >> 8;          // 0..15
    const int n    = nt * 8 + (lane >> 2);
    const int k0   = kt * 16 + 2 * (lane & 3);

    {
        const float* W = wv + n * 128;
        uint32_t h0, l0, h1, l1;
        split2(W[k0], W[k0 + 1], h0, l0);
        split2(W[k0 + 8], W[k0 + 9], h1, l1);
        g_wv_hi[idx] = make_uint2(h0, h1);
        g_wv_lo[idx] = make_uint2(l0, l1);
    }
    {
        const float* W = wf1 + n * 128;
        uint32_t h0, l0, h1, l1;
        split2(W[k0], W[k0 + 1], h0, l0);
        split2(W[k0 + 8], W[k0 + 9], h1, l1);
        g_wf1_hi[idx] = make_uint2(h0, h1);
        g_wf1_lo[idx] = make_uint2(l0, l1);
    }
    if (nt < 8) {
        const float* W = wf2 + n * 128;
        uint32_t h0, l0, h1, l1;
        split2(W[k0], W[k0 + 1], h0, l0);
        split2(W[k0 + 8], W[k0 + 9], h1, l1);
        g_wf2_hi[idx] = make_uint2(h0, h1);
        g_wf2_lo[idx] = make_uint2(l0, l1);
    }
}

// ---------------------------------------------------------------------------
// Fused kernel: value / hmid / flow GEMMs via mma.sync bf16x3.
// 256 threads (8 warps), warp grid 4(m) x 2(n). 1 CTA/SM.
// SMEM map (bytes):
//  A_HI 0 (32K) | A_LO 32768 (32K)            A fragments (also A2 after hmid)
//  65536: fp32 stage [m][k] pitch130 (66.5K)  then overwritten by:
//  BV_HI 65536 | BV_LO 98304 | BF1_HI 131072 | BF1_LO 163840
//  (after GEMM1) WF2_HI 65536 (16K) | WF2_LO 81920 (16K)
//  biases @196608: bf1[128], bf2[64], bv[128]
// ---------------------------------------------------------------------------
#define SM_A_HI   0
#define SM_A_LO   32768
#define SM_STAGE  65536
#define SM_BV_HI  65536
#define SM_BV_LO  98304
#define SM_BF1_HI 131072
#define SM_BF1_LO 163840
#define SM_WF2_HI 65536
#define SM_WF2_LO 81920
#define SM_BIASF1 196608
#define SM_BIASF2 197120
#define SM_BIASV  197408
#define FUSED_SMEM 197920

__global__ __launch_bounds__(256, 1) void fused_gemm(const float* __restrict__ u,
                                                     const float* __restrict__ bf1,
                                                     const float* __restrict__ bf2,
                                                     const float* __restrict__ bv) {
    extern __shared__ char smem[];
    const int t    = threadIdx.x;
    const int wid  = t >> 5;
    const int lane = t & 31;
    const int wm   = wid & 3;   // m group (rows 32*wm)
    const int wn   = wid >> 2;  // n group
    const int m0   = blockIdx.x * 128;
    const int b    = m0 / HWSZ;
    const int hw0  = m0 - b * HWSZ;
    const float* uB = u + (size_t)b * CINC * HWSZ + hw0;

    // ---- 1. stage u tile as fp32 [m][k] (pitch 130) + biases ----
    float* stage = (float*)(smem + SM_STAGE);
    for (int i = t; i < 128 * 32; i += 256) {
        const int k  = i >> 5;
        const int c4 = i & 31;
        const float4 v = ((const float4*)(uB + (size_t)k * HWSZ))[c4];
        const int m = 4 * c4;
        stage[(m + 0) * 130 + k] = v.x;
        stage[(m + 1) * 130 + k] = v.y;
        stage[(m + 2) * 130 + k] = v.z;
        stage[(m + 3) * 130 + k] = v.w;
    }
    if (t < 128) ((float*)(smem + SM_BIASF1))[t] = bf1[t];
    if (t < 64)  ((float*)(smem + SM_BIASF2))[t] = bf2[t];
    if (t < 128) ((float*)(smem + SM_BIASV))[t]  = bv[t];
    __syncthreads();

    // ---- 2. convert A tile -> hi/lo fragments (warp wid handles kt=wid) ----
    {
        const int kt = wid;
        const int kk = kt * 16 + 2 * (lane & 3);
        uint4* AH = (uint4*)(smem + SM_A_HI);
        uint4* AL = (uint4*)(smem + SM_A_LO);
#pragma unroll
        for (int mt = 0; mt < 8; ++mt) {
            const int row = mt * 16 + (lane >> 2);
            const float2 v0 = *(const float2*)&stage[row * 130 + kk];
            const float2 v1 = *(const float2*)&stage[(row + 8) * 130 + kk];
            const float2 v2 = *(const float2*)&stage[row * 130 + kk + 8];
            const float2 v3 = *(const float2*)&stage[(row + 8) * 130 + kk + 8];
            uint4 H, L;
            split2(v0.x, v0.y, H.x, L.x);
            split2(v1.x, v1.y, H.y, L.y);
            split2(v2.x, v2.y, H.z, L.z);
            split2(v3.x, v3.y, H.w, L.w);
            const int slot = (mt * 8 + kt) * 32 + lane;
            AH[slot] = H;
            AL[slot] = L;
        }
    }
    __syncthreads();  // stage reads done; B copies may overwrite

    // ---- 3. copy weight fragments to smem ----
    {
        uint4* d0 = (uint4*)(smem + SM_BV_HI);
        uint4* d1 = (uint4*)(smem + SM_BV_LO);
        uint4* d2 = (uint4*)(smem + SM_BF1_HI);
        uint4* d3 = (uint4*)(smem + SM_BF1_LO);
        const uint4* s0 = (const uint4*)g_wv_hi;
        const uint4* s1 = (const uint4*)g_wv_lo;
        const uint4* s2 = (const uint4*)g_wf1_hi;
        const uint4* s3 = (const uint4*)g_wf1_lo;
        for (int i = t; i < 2048; i += 256) {
            d0[i] = s0[i]; d1[i] = s1[i]; d2[i] = s2[i]; d3[i] = s3[i];
        }
    }
    __syncthreads();

    const float* bf1s = (const float*)(smem + SM_BIASF1);
    const float* bf2s = (const float*)(smem + SM_BIASF2);
    const float* bvs  = (const float*)(smem + SM_BIASV);

    // ---- 4. value GEMM (N=128), 3 bf16x3 terms ----
    {
        float cv[2][8][4];
#pragma unroll
        for (int i = 0; i < 2; ++i)
#pragma unroll
            for (int nt = 0; nt < 8; ++nt)
#pragma unroll
                for (int r = 0; r < 4; ++r) cv[i][nt][r] = 0.0f;

#pragma unroll
        for (int term = 0; term < 3; ++term) {
            const uint4* Af = (const uint4*)(smem + (term == 2 ? SM_A_LO : SM_A_HI));
            const uint2* Bf = (const uint2*)(smem + (term == 1 ? SM_BV_LO : SM_BV_HI));
#pragma unroll
            for (int kt = 0; kt < 8; ++kt) {
                const uint4 A0 = Af[((2 * wm + 0) * 8 + kt) * 32 + lane];
                const uint4 A1 = Af[((2 * wm + 1) * 8 + kt) * 32 + lane];
#pragma unroll
                for (int nt = 0; nt < 8; ++nt) {
                    const uint2 B = Bf[((8 * wn + nt) * 8 + kt) * 32 + lane];
                    mma16816(cv[0][nt], A0.x, A0.y, A0.z, A0.w, B.x, B.y);
                    mma16816(cv[1][nt], A1.x, A1.y, A1.z, A1.w, B.x, B.y);
                }
            }
        }
        // value epilogue -> g_value (float2, head-interleaved)
        const size_t bOff = (size_t)b * HWSZ * COUTC;
#pragma unroll
        for (int i = 0; i < 2; ++i) {
            const int hwr = hw0 + 32 * wm + 16 * i + (lane >> 2);
#pragma unroll
            for (int nt = 0; nt < 8; ++nt) {
                const int n0   = 64 * wn + 8 * nt + 2 * (lane & 3);
                const int head = n0 >> 2;
                const int ci   = n0 & 3;
                const float bb0 = bvs[n0], bb1 = bvs[n0 + 1];
                float2 s0, s1;
                s0.x = cv[i][nt][0] + bb0; s0.y = cv[i][nt][1] + bb1;
                s1.x = cv[i][nt][2] + bb0; s1.y = cv[i][nt][3] + bb1;
                *(float2*)&g_value[bOff + ((size_t)head * HWSZ + hwr) * 4 + ci]       = s0;
                *(float2*)&g_value[bOff + ((size_t)head * HWSZ + hwr + 8) * 4 + ci]   = s1;
            }
        }
    }

    // ---- 5. hmid GEMM (N=128) ----
    float ch[2][8][4];
#pragma unroll
    for (int i = 0; i < 2; ++i)
#pragma unroll
        for (int nt = 0; nt < 8; ++nt)
#pragma unroll
            for (int r = 0; r < 4; ++r) ch[i][nt][r] = 0.0f;

#pragma unroll
    for (int term = 0; term < 3; ++term) {
        const uint4* Af = (const uint4*)(smem + (term == 2 ? SM_A_LO : SM_A_HI));
        const uint2* Bf = (const uint2*)(smem + (term == 1 ? SM_BF1_LO : SM_BF1_HI));
#pragma unroll
        for (int kt = 0; kt < 8; ++kt) {
            const uint4 A0 = Af[((2 * wm + 0) * 8 + kt) * 32 + lane];
            const uint4 A1 = Af[((2 * wm + 1) * 8 + kt) * 32 + lane];
#pragma unroll
            for (int nt = 0; nt < 8; ++nt) {
                const uint2 B = Bf[((8 * wn + nt) * 8 + kt) * 32 + lane];
                mma16816(ch[0][nt], A0.x, A0.y, A0.z, A0.w, B.x, B.y);
                mma16816(ch[1][nt], A1.x, A1.y, A1.z, A1.w, B.x, B.y);
            }
        }
    }
    __syncthreads();  // all warps done reading A fragments

    // ---- 6. hmid -> relu -> bf16 split -> A2 fragments (reuse A region) ----
    // C frag (rows lane/4, cols 2*(lane%4)) maps 1:1 onto A frag ownership.
    {
        uint4* AH = (uint4*)(smem + SM_A_HI);
        uint4* AL = (uint4*)(smem + SM_A_LO);
#pragma unroll
        for (int i = 0; i < 2; ++i) {
            const int mtg = 2 * wm + i;
#pragma unroll
            for (int kl = 0; kl < 4; ++kl) {
                const int ktg = 4 * wn + kl;
                const int nt0 = 2 * kl, nt1 = nt0 + 1;
                const int n00 = 64 * wn + 8 * nt0 + 2 * (lane & 3);
                const int n10 = n00 + 8;
                const float b00 = bf1s[n00], b01 = bf1s[n00 + 1];
                const float b10 = bf1s[n10], b11 = bf1s[n10 + 1];
                uint4 H, L;
                split2(fmaxf(ch[i][nt0][0] + b00, 0.0f),
                       fmaxf(ch[i][nt0][1] + b01, 0.0f), H.x, L.x);
                split2(fmaxf(ch[i][nt0][2] + b00, 0.0f),
                       fmaxf(ch[i][nt0][3] + b01, 0.0f), H.y, L.y);
                split2(fmaxf(ch[i][nt1][0] + b10, 0.0f),
                       fmaxf(ch[i][nt1][1] + b11, 0.0f), H.z, L.z);
                split2(fmaxf(ch[i][nt1][2] + b10, 0.0f),
                       fmaxf(ch[i][nt1][3] + b11, 0.0f), H.w, L.w);
                const int slot = (mtg * 8 + ktg) * 32 + lane;
                AH[slot] = H;
                AL[slot] = L;
            }
        }
        // copy wf2 fragments (BV region dead)
        uint4* d0 = (uint4*)(smem + SM_WF2_HI);
        uint4* d1 = (uint4*)(smem + SM_WF2_LO);
        const uint4* s0 = (const uint4*)g_wf2_hi;
        const uint4* s1 = (const uint4*)g_wf2_lo;
        for (int i2 = t; i2 < 1024; i2 += 256) { d0[i2] = s0[i2]; d1[i2] = s1[i2]; }
    }
    __syncthreads();

    // ---- 7. flow GEMM (N=64, warp tile 32x32) + epilogue ----
    {
        float cf[2][4][4];
#pragma unroll
        for (int i = 0; i < 2; ++i)
#pragma unroll
            for (int j = 0; j < 4; ++j)
#pragma unroll
                for (int r = 0; r < 4; ++r) cf[i][j][r] = 0.0f;

#pragma unroll
        for (int term = 0; term < 3; ++term) {
            const uint4* Af = (const uint4*)(smem + (term == 2 ? SM_A_LO : SM_A_HI));
            const uint2* Bf = (const uint2*)(smem + (term == 1 ? SM_WF2_LO : SM_WF2_HI));
#pragma unroll
            for (int kt = 0; kt < 8; ++kt) {
                const uint4 A0 = Af[((2 * wm + 0) * 8 + kt) * 32 + lane];
                const uint4 A1 = Af[((2 * wm + 1) * 8 + kt) * 32 + lane];
#pragma unroll
                for (int j = 0; j < 4; ++j) {
                    const uint2 B = Bf[((4 * wn + j) * 8 + kt) * 32 + lane];
                    mma16816(cf[0][j], A0.x, A0.y, A0.z, A0.w, B.x, B.y);
                    mma16816(cf[1][j], A1.x, A1.y, A1.z, A1.w, B.x, B.y);
                }
            }
        }
#pragma unroll
        for (int i = 0; i < 2; ++i) {
            const int mr = m0 + 32 * wm + 16 * i + (lane >> 2);
#pragma unroll
            for (int j = 0; j < 4; ++j) {
                const int n0 = 32 * wn + 8 * j + 2 * (lane & 3);
                g_flow[(size_t)n0 * TOT + mr]           = cf[i][j][0] + bf2s[n0];
                g_flow[(size_t)(n0 + 1) * TOT + mr]     = cf[i][j][1] + bf2s[n0 + 1];
                g_flow[(size_t)n0 * TOT + mr + 8]       = cf[i][j][2] + bf2s[n0];
                g_flow[(size_t)(n0 + 1) * TOT + mr + 8] = cf[i][j][3] + bf2s[n0 + 1];
            }
        }
    }
}

// ---------------------------------------------------------------------------
// Kernel 3: periodic bilinear warp. One lane per (pixel, head).
// ---------------------------------------------------------------------------
__global__ __launch_bounds__(256) void sample_kernel(float* __restrict__ out) {
    const int gt    = blockIdx.x * 256 + threadIdx.x;
    const int lane  = gt & 31;
    const int strip = gt >> 5;
    const int chunk = strip & (HWSZ / 32 - 1);
    const int bh    = strip >> 11;             // b*HEADS + head
    const int head  = bh & (HEADS - 1);
    const int b     = bh >> 5;
    const int hw    = chunk * 32 + lane;
    const int h     = hw >> 8;
    const int w     = hw & 255;
    const size_t m  = (size_t)b * HWSZ + hw;

    const float fx = g_flow[(size_t)(head * 2) * TOT + m];
    const float fy = g_flow[(size_t)(head * 2 + 1) * TOT + m];

    const float gx = -1.0f + (2.0f / 255.0f) * (float)w + fx;
    const float gy = -1.0f + (2.0f / 255.0f) * (float)h + fy;

    const float ax = ((gx + 1.0f) * 256.0f - 1.0f) * 0.5f;
    const float ay = ((gy + 1.0f) * 256.0f - 1.0f) * 0.5f;

    float px = fmodf(ax, 256.0f); if (px < 0.0f) px += 256.0f;
    float py = fmodf(ay, 256.0f); if (py < 0.0f) py += 256.0f;

    const float x0f = floorf(px), y0f = floorf(py);
    const float wx = px - x0f, wy = py - y0f;
    int x0 = (int)x0f; x0 = x0 < 0 ? 0 : (x0 > 255 ? 255 : x0);
    int y0 = (int)y0f; y0 = y0 < 0 ? 0 : (y0 > 255 ? 255 : y0);
    const int x1 = (x0 + 1) & 255;
    const int y1 = (y0 + 1) & 255;

    const float4* vp = (const float4*)g_value + (size_t)bh * HWSZ;
    const float4 v00 = vp[y0 * 256 + x0];
    const float4 v01 = vp[y0 * 256 + x1];
    const float4 v10 = vp[y1 * 256 + x0];
    const float4 v11 = vp[y1 * 256 + x1];

    const float w00 = (1.0f - wx) * (1.0f - wy);
    const float w01 = wx * (1.0f - wy);
    const float w10 = (1.0f - wx) * wy;
    const float w11 = wx * wy;

    const float o0 = v00.x * w00 + v01.x * w01 + v10.x * w10 + v11.x * w11;
    const float o1 = v00.y * w00 + v01.y * w01 + v10.y * w10 + v11.y * w11;
    const float o2 = v00.z * w00 + v01.z * w01 + v10.z * w10 + v11.z * w11;
    const float o3 = v00.w * w00 + v01.w * w01 + v10.w * w10 + v11.w * w11;

    float* outp = out + ((size_t)b * COUTC + head * 4) * HWSZ + hw;
    outp[0]        = o0;
    outp[HWSZ]     = o1;
    outp[2 * HWSZ] = o2;
    outp[3 * HWSZ] = o3;
}

// ---------------------------------------------------------------------------
extern "C" void kernel_launch(void* const* d_in, const int* in_sizes, int n_in,
                              void* d_out, int out_size) {
    const float* u   = (const float*)d_in[0];
    const float* wf1 = (const float*)d_in[1];
    const float* bf1 = (const float*)d_in[2];
    const float* wf2 = (const float*)d_in[3];
    const float* bf2 = (const float*)d_in[4];
    const float* wv  = (const float*)d_in[5];
    const float* bv  = (const float*)d_in[6];
    float* out = (float*)d_out;

    cudaFuncSetAttribute(fused_gemm, cudaFuncAttributeMaxDynamicSharedMemorySize,
                         FUSED_SMEM);

    split_weights<<<16, 256>>>(wv, wf1, wf2);
    fused_gemm<<<TOT / 128, 256, FUSED_SMEM>>>(u, bf1, bf2, bv);

    const long long items = (long long)BQ * HEADS * HWSZ;  // 16.78M
    sample_kernel<<<(int)(items / 256), 256>>>(out);
}